// round 12
// baseline (speedup 1.0000x reference)
#include <cuda_runtime.h>
#include <math.h>

#define NTHREADS 256
#define NW 8            // warps per block = probes per round
#define NCLS 1000
#define NT 800
#define TSTEP 0.00125f
#define TOL 0.01f
#define L2E 1.4426950408889634f

__device__ __forceinline__ float ex2(float x) {
    float y;
    asm("ex2.approx.f32 %0, %1;" : "=f"(y) : "f"(x));
    return y;
}

__global__ __launch_bounds__(NTHREADS)
void logit_compression_kernel(const float* __restrict__ logits,
                              float* __restrict__ out) {
    __shared__ float rsm[1024];          // raw logits, padded with -inf
    __shared__ float wmax[NW], wsum[NW];
    __shared__ float ctbuf[2][NW];
    __shared__ float sbuf[2][NW];

    const int tid  = threadIdx.x;
    const int lane = tid & 31;
    const int w    = tid >> 5;
    const int row  = blockIdx.x;
    const float* lrow = logits + row * NCLS;
    float* orow = out + row * NCLS;

    // ---- load row as float4 (1000 = 250 float4, rows 16B-aligned) ----
    float4 rv;
    if (tid < 250) rv = ((const float4*)lrow)[tid];
    else           rv = make_float4(-INFINITY, -INFINITY, -INFINITY, -INFINITY);
    ((float4*)rsm)[tid] = rv;            // publish raw row (padding = -inf)

    // ---- fused per-warp (max, sum), single setup barrier ----
    float mw = fmaxf(fmaxf(rv.x, rv.y), fmaxf(rv.z, rv.w));
#pragma unroll
    for (int o = 16; o > 0; o >>= 1) mw = fmaxf(mw, __shfl_xor_sync(0xffffffffu, mw, o));
    float sw = (__expf(rv.x - mw) + __expf(rv.y - mw))
             + (__expf(rv.z - mw) + __expf(rv.w - mw));
#pragma unroll
    for (int o = 16; o > 0; o >>= 1) sw += __shfl_xor_sync(0xffffffffu, sw, o);
    if (lane == 0) { wmax[w] = mw; wsum[w] = sw; }
    __syncthreads();                     // publishes rsm too

    // all threads redundantly combine (fixed tree, deterministic)
    float m = fmaxf(fmaxf(fmaxf(wmax[0], wmax[1]), fmaxf(wmax[2], wmax[3])),
                    fmaxf(fmaxf(wmax[4], wmax[5]), fmaxf(wmax[6], wmax[7])));
    float t0 = wsum[0] * __expf(wmax[0] - m), t1 = wsum[1] * __expf(wmax[1] - m);
    float t2 = wsum[2] * __expf(wmax[2] - m), t3 = wsum[3] * __expf(wmax[3] - m);
    float t4 = wsum[4] * __expf(wmax[4] - m), t5 = wsum[5] * __expf(wmax[5] - m);
    float t6 = wsum[6] * __expf(wmax[6] - m), t7 = wsum[7] * __expf(wmax[7] - m);
    const float S1 = ((t0 + t1) + (t2 + t3)) + ((t4 + t5) + (t6 + t7));

    // ---- conf, bin, target confidence ----
    const float conf = __fdiv_rn(1.0f, S1);
    int bi = (conf >= (2.0f / 3.0f)) ? 2 : (conf >= (1.0f / 3.0f)) ? 1 : 0;
    const float BL  = (bi == 0) ? 0.0f : (bi == 1) ? (1.0f / 3.0f) : (2.0f / 3.0f);
    const float NBL = (bi == 0) ? 0.8f : (bi == 1) ? 0.86666666666f : 0.93333333333f;
    const float nc  = __fadd_rn(NBL,
                     __fmul_rn((float)(1.0 / 15.0),
                               __fdiv_rn(__fsub_rn(conf, BL), 0.2666666667f)));
    const float Sthr = __fdiv_rn(1.0f, __fsub_rn(nc, TOL));   // guidance only

    // ---- search for first j with ct(j) >= nc - TOL, ct = 1/S(u_j), monotone.
    // Round 0: structural table (nc >= 0.8 => late crossings for soft rows).
    // Round 1: if bracketed, secant on log(S-1) vs u, 8 CONSECUTIVE probes
    // (fail->pass adjacency terminates). Rounds >=2 (and unbracketed round 1):
    // uniform stride (proven fallback; guarantees progress and correctness).
    const float4* r4 = (const float4*)rsm;
    const int P0[NW] = {480, 640, 704, 744, 768, 784, 794, 799};  // ascending

    int lo = 0, hi = NT;
    float ct_hi = 0.0f, s_hi = 0.0f;
    int   p_lo = -1;  float s_lo = 0.0f;
    int par = 0, iter = 0;

    while (lo < hi) {
        const int stride = (hi - lo + NW - 1) >> 3;
        const bool tab = (iter == 0);
        const bool itp = (iter == 1) && (p_lo >= 0) && (hi < NT);

        int q = 0;
        if (itp) {
            // secant on y(u) = log(S-1); identical on all threads.
            float u1 = __frcp_rn(__fsub_rn(1.0f, __fmul_rn(TSTEP, (float)p_lo)));
            float u2 = __frcp_rn(__fsub_rn(1.0f, __fmul_rn(TSTEP, (float)hi)));
            float y1 = __logf(s_lo - 1.0f);
            float y2 = __logf(s_hi - 1.0f);
            float yt = __logf(Sthr - 1.0f);
            float fr = (y1 - yt) / (y1 - y2);
            float jp = (isfinite(fr) && fr >= 0.0f && fr <= 1.5f)
                     ? (1.0f - __frcp_rn(u1 + fr * (u2 - u1))) * 800.0f
                     : 0.5f * (float)(lo + hi);
            int jpi = (int)ceilf(jp) - 2;
            int qmax = hi - NW; if (qmax < lo) qmax = lo;
            q = (jpi < lo) ? lo : ((jpi > qmax) ? qmax : jpi);
        }

        int pos; bool active;
        if (tab)      { pos = P0[w];           active = true; }
        else if (itp) { pos = q + w;           active = (pos < hi); }
        else          { pos = lo + w * stride; active = (pos < hi); }

        float ctv = 0.0f, sv = 0.0f;
        if (active) {                                 // warp-uniform branch
            float t    = __fsub_rn(1.0f, __fmul_rn(TSTEP, (float)pos));
            float invt = __frcp_rn(t);
            float c2   = __fmul_rn(invt, L2E);        // log2(e)/t
            float mc2  = -m * c2;                     // term = ex2(r*c2 - m*c2)
            float a0 = 0.0f, a1 = 0.0f, a2 = 0.0f, a3 = 0.0f;
#pragma unroll
            for (int k = 0; k < 8; k++) {
                float4 v = r4[lane + k * 32];
                a0 += ex2(fmaf(v.x, c2, mc2));
                a1 += ex2(fmaf(v.y, c2, mc2));
                a2 += ex2(fmaf(v.z, c2, mc2));
                a3 += ex2(fmaf(v.w, c2, mc2));
            }
            float s = (a0 + a1) + (a2 + a3);
#pragma unroll
            for (int o = 16; o > 0; o >>= 1) s += __shfl_xor_sync(0xffffffffu, s, o);
            sv  = s;
            ctv = __frcp_rn(s);                       // ct = 1/S
        }
        if (lane == 0) { ctbuf[par][w] = ctv; sbuf[par][w] = sv; }
        __syncthreads();   // single barrier per round (double-buffered)

        // Deterministic redundant interval update.
        int first = -1, previ = -1, lasti = -1;
        int pprev = 0, pfirst = 0, plast = 0;
#pragma unroll
        for (int i = 0; i < NW; i++) {
            int p  = tab ? P0[i] : (itp ? (q + i) : (lo + i * stride));
            bool a = tab ? true  : (p < hi);
            if (a) {
                if (first < 0) {
                    if (__fsub_rn(ctbuf[par][i], nc) >= -TOL) { first = i; pfirst = p; }
                    else { previ = i; pprev = p; }
                }
                lasti = i; plast = p;
            }
        }
        if (first >= 0) {
            ct_hi = ctbuf[par][first];
            s_hi  = sbuf[par][first];
            hi = pfirst;
            if (previ >= 0) { p_lo = pprev; s_lo = sbuf[par][previ]; lo = pprev + 1; }
            // first == 0: lo unchanged (crossing may precede lowest probe)
        } else {
            p_lo = plast; s_lo = sbuf[par][lasti];
            lo = plast + 1;
        }
        par ^= 1;
        iter++;
    }

    // ---- band check + output (float4 stores) ----
    float sc = 1.0f;
    if (hi < NT) {
        float g = __fsub_rn(ct_hi, nc);               // >= -TOL by construction
        if (fabsf(g) <= TOL) {
            float tj = __fsub_rn(1.0f, __fmul_rn(TSTEP, (float)hi));
            sc = __frcp_rn(tj);                       // out = r * (1/tj)
        }
    }
    if (tid < 250) {
        float4 o;
        o.x = rv.x * sc; o.y = rv.y * sc; o.z = rv.z * sc; o.w = rv.w * sc;
        ((float4*)orow)[tid] = o;
    }
}

extern "C" void kernel_launch(void* const* d_in, const int* in_sizes, int n_in,
                              void* d_out, int out_size) {
    const float* logits = (const float*)d_in[0];
    float* out = (float*)d_out;
    int B = in_sizes[0] / NCLS;   // 128 rows
    logit_compression_kernel<<<B, NTHREADS>>>(logits, out);
}

// round 13
// speedup vs baseline: 1.1922x; 1.1922x over previous
#include <cuda_runtime.h>
#include <math.h>

#define NTHREADS 256
#define NW 8            // warps per block = probes per round
#define NCLS 1000
#define NT 800
#define TSTEP 0.00125f
#define TOL 0.01f
#define L2E 1.4426950408889634f

__device__ __forceinline__ float ex2(float x) {
    float y;
    asm("ex2.approx.f32 %0, %1;" : "=f"(y) : "f"(x));
    return y;
}

__global__ __launch_bounds__(NTHREADS)
void logit_compression_kernel(const float* __restrict__ logits,
                              float* __restrict__ out) {
    __shared__ float rsm[1024];          // raw logits, padded with -inf
    __shared__ float wmax[NW], wsum[NW];
    __shared__ float ctbuf[2][NW];

    const int tid  = threadIdx.x;
    const int lane = tid & 31;
    const int w    = tid >> 5;
    const int row  = blockIdx.x;
    const float* lrow = logits + row * NCLS;
    float* orow = out + row * NCLS;

    // ---- load row as float4 (1000 = 250 float4, rows 16B-aligned) ----
    float4 rv;
    if (tid < 250) rv = ((const float4*)lrow)[tid];
    else           rv = make_float4(-INFINITY, -INFINITY, -INFINITY, -INFINITY);
    ((float4*)rsm)[tid] = rv;            // publish raw row (padding = -inf)

    // ---- fused per-warp (max, sum) then single barrier ----
    float mw = fmaxf(fmaxf(rv.x, rv.y), fmaxf(rv.z, rv.w));
#pragma unroll
    for (int o = 16; o > 0; o >>= 1) mw = fmaxf(mw, __shfl_xor_sync(0xffffffffu, mw, o));
    // warp-local softmax sum relative to warp max (exp(-inf)==0 for padding)
    float sw = (__expf(rv.x - mw) + __expf(rv.y - mw))
             + (__expf(rv.z - mw) + __expf(rv.w - mw));
#pragma unroll
    for (int o = 16; o > 0; o >>= 1) sw += __shfl_xor_sync(0xffffffffu, sw, o);
    if (lane == 0) { wmax[w] = mw; wsum[w] = sw; }
    __syncthreads();                     // single setup barrier: publishes rsm too

    // all threads redundantly combine (fixed tree, deterministic)
    float m = fmaxf(fmaxf(fmaxf(wmax[0], wmax[1]), fmaxf(wmax[2], wmax[3])),
                    fmaxf(fmaxf(wmax[4], wmax[5]), fmaxf(wmax[6], wmax[7])));
    float t0 = wsum[0] * __expf(wmax[0] - m), t1 = wsum[1] * __expf(wmax[1] - m);
    float t2 = wsum[2] * __expf(wmax[2] - m), t3 = wsum[3] * __expf(wmax[3] - m);
    float t4 = wsum[4] * __expf(wmax[4] - m), t5 = wsum[5] * __expf(wmax[5] - m);
    float t6 = wsum[6] * __expf(wmax[6] - m), t7 = wsum[7] * __expf(wmax[7] - m);
    const float S1 = ((t0 + t1) + (t2 + t3)) + ((t4 + t5) + (t6 + t7));

    // ---- conf, bin, target confidence ----
    const float conf = __fdiv_rn(1.0f, S1);
    int bi = (conf >= (2.0f / 3.0f)) ? 2 : (conf >= (1.0f / 3.0f)) ? 1 : 0;
    const float BL  = (bi == 0) ? 0.0f : (bi == 1) ? (1.0f / 3.0f) : (2.0f / 3.0f);
    const float NBL = (bi == 0) ? 0.8f : (bi == 1) ? 0.86666666666f : 0.93333333333f;
    const float nc  = __fadd_rn(NBL,
                     __fmul_rn((float)(1.0 / 15.0),
                               __fdiv_rn(__fsub_rn(conf, BL), 0.2666666667f)));

    // ---- search for first j with ct(j) >= nc - TOL, ct = 1/S(u_j) ----
    // ct(j) monotone non-decreasing in j (temps decrease, each term shrinks,
    // fixed summation tree preserves order). Round 0: structural table
    // (nc >= 0.8 always => late crossings); fallback: uniform stride.
    const float4* r4 = (const float4*)rsm;
    const int P0[NW] = {480, 600, 672, 720, 752, 776, 792, 799};  // ascending

    int lo = 0, hi = NT;
    float ct_hi = 0.0f;
    int par = 0;
    bool tab = true;

    while (lo < hi) {
        const int stride = (hi - lo + NW - 1) >> 3;
        int pos; bool active;
        if (tab) { pos = P0[w];           active = true; }
        else     { pos = lo + w * stride; active = (pos < hi); }

        float ctv = 0.0f;
        if (active) {                                 // warp-uniform branch
            float t    = __fsub_rn(1.0f, __fmul_rn(TSTEP, (float)pos));
            float invt = __frcp_rn(t);
            float c2   = __fmul_rn(invt, L2E);        // log2(e)/t
            float mc2  = -m * c2;                     // term = ex2(r*c2 - m*c2)
            float a0 = 0.0f, a1 = 0.0f, a2 = 0.0f, a3 = 0.0f;
#pragma unroll
            for (int k = 0; k < 8; k++) {
                float4 v = r4[lane + k * 32];
                a0 += ex2(fmaf(v.x, c2, mc2));
                a1 += ex2(fmaf(v.y, c2, mc2));
                a2 += ex2(fmaf(v.z, c2, mc2));
                a3 += ex2(fmaf(v.w, c2, mc2));
            }
            float s = (a0 + a1) + (a2 + a3);
#pragma unroll
            for (int o = 16; o > 0; o >>= 1) s += __shfl_xor_sync(0xffffffffu, s, o);
            ctv = __frcp_rn(s);                       // ct = 1/S
        }
        if (lane == 0) ctbuf[par][w] = ctv;
        __syncthreads();   // single barrier per round (double-buffered ctbuf)

        // Deterministic redundant interval update.
        int first = -1;
        int pprev = 0, pfirst = 0, plast = 0;
#pragma unroll
        for (int i = 0; i < NW; i++) {
            int p  = tab ? P0[i] : (lo + i * stride);
            bool a = tab ? true  : (p < hi);
            if (a) {
                if (first < 0) {
                    if (__fsub_rn(ctbuf[par][i], nc) >= -TOL) { first = i; pfirst = p; }
                    else pprev = p;
                }
                plast = p;
            }
        }
        if (first >= 0) {
            ct_hi = ctbuf[par][first];
            hi = pfirst;
            if (first > 0) lo = pprev + 1;
            // first == 0 on table round: crossing may be < P0[0]; lo unchanged
        } else {
            lo = plast + 1;
        }
        par ^= 1;
        tab = false;
    }

    // ---- band check + output (float4 stores) ----
    float sc = 1.0f;
    if (hi < NT) {
        float g = __fsub_rn(ct_hi, nc);               // >= -TOL by construction
        if (fabsf(g) <= TOL) {
            float tj = __fsub_rn(1.0f, __fmul_rn(TSTEP, (float)hi));
            sc = __frcp_rn(tj);                       // out = r * (1/tj)
        }
    }
    if (tid < 250) {
        float4 o;
        o.x = rv.x * sc; o.y = rv.y * sc; o.z = rv.z * sc; o.w = rv.w * sc;
        ((float4*)orow)[tid] = o;
    }
}

extern "C" void kernel_launch(void* const* d_in, const int* in_sizes, int n_in,
                              void* d_out, int out_size) {
    const float* logits = (const float*)d_in[0];
    float* out = (float*)d_out;
    int B = in_sizes[0] / NCLS;   // 128 rows
    logit_compression_kernel<<<B, NTHREADS>>>(logits, out);
}

// round 14
// speedup vs baseline: 1.2316x; 1.0331x over previous
#include <cuda_runtime.h>
#include <math.h>

#define NTHREADS 256
#define NW 8            // warps per block = probes per round
#define NCLS 1000
#define NT 800
#define TSTEP 0.00125f
#define TOL 0.01f
#define L2E 1.4426950408889634f

__device__ __forceinline__ float ex2(float x) {
    float y;
    asm("ex2.approx.f32 %0, %1;" : "=f"(y) : "f"(x));
    return y;
}

// Table probe positions (ascending) and their c2 = log2(e)/t constants.
__device__ __constant__ const int P0[NW] = {480, 600, 672, 720, 752, 776, 792, 799};
// t = 1 - 0.00125*P0 = {0.4, 0.25, 0.16, 0.1, 0.06, 0.03, 0.01, 0.00125}
#define C2_0 3.6067376022224085f
#define C2_1 5.770780163555854f
#define C2_2 9.016844005556021f
#define C2_3 14.426950408889634f
#define C2_4 24.04491734814939f
#define C2_5 48.08983469629878f
#define C2_6 144.26950408889635f
#define C2_7 1154.1560327111707f

__global__ __launch_bounds__(NTHREADS)
void logit_compression_kernel(const float* __restrict__ logits,
                              float* __restrict__ out) {
    __shared__ float rsm[1024];          // raw logits, padded with -inf
    __shared__ float wmax[NW];
    __shared__ float wpart[9][NW];       // [0]=S1 partials, [1..8]=table partials
    __shared__ float ctbuf[2][NW];

    const int tid  = threadIdx.x;
    const int lane = tid & 31;
    const int w    = tid >> 5;
    const int row  = blockIdx.x;
    const float* lrow = logits + row * NCLS;
    float* orow = out + row * NCLS;

    // ---- load row as float4 (1000 = 250 float4, rows 16B-aligned) ----
    float4 rv;
    if (tid < 250) rv = ((const float4*)lrow)[tid];
    else           rv = make_float4(-INFINITY, -INFINITY, -INFINITY, -INFINITY);
    ((float4*)rsm)[tid] = rv;            // publish raw row (padding = -inf)

    // ---- warp max ----
    float mw = fmaxf(fmaxf(rv.x, rv.y), fmaxf(rv.z, rv.w));
#pragma unroll
    for (int o = 16; o > 0; o >>= 1) mw = fmaxf(mw, __shfl_xor_sync(0xffffffffu, mw, o));

    // ---- 9 warp-local partial sums from REGISTERS (S1 + 8 table temps) ----
    const float C2[9] = {L2E, C2_0, C2_1, C2_2, C2_3, C2_4, C2_5, C2_6, C2_7};
    float dx0 = rv.x - mw, dx1 = rv.y - mw, dx2 = rv.z - mw, dx3 = rv.w - mw;
    float acc[9];
#pragma unroll
    for (int i = 0; i < 9; i++) {
        acc[i] = (ex2(dx0 * C2[i]) + ex2(dx1 * C2[i]))
               + (ex2(dx2 * C2[i]) + ex2(dx3 * C2[i]));   // ex2(-inf)=0 padding
    }
#pragma unroll
    for (int o = 16; o > 0; o >>= 1) {
#pragma unroll
        for (int i = 0; i < 9; i++) acc[i] += __shfl_xor_sync(0xffffffffu, acc[i], o);
    }
    if (lane == 0) {
        wmax[w] = mw;
#pragma unroll
        for (int i = 0; i < 9; i++) wpart[i][w] = acc[i];
    }
    __syncthreads();                     // single setup barrier: publishes rsm too

    // ---- combine (all threads redundantly, fixed tree; S1 bit-identical to R13) ----
    float m = fmaxf(fmaxf(fmaxf(wmax[0], wmax[1]), fmaxf(wmax[2], wmax[3])),
                    fmaxf(fmaxf(wmax[4], wmax[5]), fmaxf(wmax[6], wmax[7])));
    float t0 = wpart[0][0] * __expf(wmax[0] - m), t1 = wpart[0][1] * __expf(wmax[1] - m);
    float t2 = wpart[0][2] * __expf(wmax[2] - m), t3 = wpart[0][3] * __expf(wmax[3] - m);
    float t4 = wpart[0][4] * __expf(wmax[4] - m), t5 = wpart[0][5] * __expf(wmax[5] - m);
    float t6 = wpart[0][6] * __expf(wmax[6] - m), t7 = wpart[0][7] * __expf(wmax[7] - m);
    const float S1 = ((t0 + t1) + (t2 + t3)) + ((t4 + t5) + (t6 + t7));

    const float conf = __fdiv_rn(1.0f, S1);
    int bi = (conf >= (2.0f / 3.0f)) ? 2 : (conf >= (1.0f / 3.0f)) ? 1 : 0;
    const float BL  = (bi == 0) ? 0.0f : (bi == 1) ? (1.0f / 3.0f) : (2.0f / 3.0f);
    const float NBL = (bi == 0) ? 0.8f : (bi == 1) ? 0.86666666666f : 0.93333333333f;
    const float nc  = __fadd_rn(NBL,
                     __fmul_rn((float)(1.0 / 15.0),
                               __fdiv_rn(__fsub_rn(conf, BL), 0.2666666667f)));

    // ---- warp w reconstructs its table probe S(u_w) and publishes ct ----
    {
        float c2w = C2[w + 1];
        float sb = 0.0f;
#pragma unroll
        for (int i = 0; i < NW; i++)
            sb = fmaf(wpart[w + 1][i], ex2((wmax[i] - m) * c2w), sb);  // fixed order
        if (lane == 0) ctbuf[0][w] = __frcp_rn(sb);
    }
    __syncthreads();

    // ---- table-round scan (positions P0; ct monotone in j within this scheme:
    // every factor ex2(d*c2) is non-increasing in u for d<=0) ----
    int lo = 0, hi = NT;
    float ct_hi = 0.0f;
    {
        int first = -1; int pprev = 0, pfirst = 0;
#pragma unroll
        for (int i = 0; i < NW; i++) {
            if (first < 0) {
                if (__fsub_rn(ctbuf[0][i], nc) >= -TOL) { first = i; pfirst = P0[i]; }
                else pprev = P0[i];
            }
        }
        if (first >= 0) {
            ct_hi = ctbuf[0][first];
            hi = pfirst;
            if (first > 0) lo = pprev + 1;
            // first == 0: crossing may precede P0[0]; lo stays 0
        } else {
            lo = P0[NW - 1] + 1;         // 800 -> loop skipped, "not found"
        }
    }

    // ---- uniform-stride rounds (verbatim champion fallback) ----
    const float4* r4 = (const float4*)rsm;
    int par = 1;
    while (lo < hi) {
        const int stride = (hi - lo + NW - 1) >> 3;
        const int pos = lo + w * stride;
        const bool active = (pos < hi);

        float ctv = 0.0f;
        if (active) {                                 // warp-uniform branch
            float t    = __fsub_rn(1.0f, __fmul_rn(TSTEP, (float)pos));
            float invt = __frcp_rn(t);
            float c2   = __fmul_rn(invt, L2E);
            float mc2  = -m * c2;
            float a0 = 0.0f, a1 = 0.0f, a2 = 0.0f, a3 = 0.0f;
#pragma unroll
            for (int k = 0; k < 8; k++) {
                float4 v = r4[lane + k * 32];
                a0 += ex2(fmaf(v.x, c2, mc2));
                a1 += ex2(fmaf(v.y, c2, mc2));
                a2 += ex2(fmaf(v.z, c2, mc2));
                a3 += ex2(fmaf(v.w, c2, mc2));
            }
            float s = (a0 + a1) + (a2 + a3);
#pragma unroll
            for (int o = 16; o > 0; o >>= 1) s += __shfl_xor_sync(0xffffffffu, s, o);
            ctv = __frcp_rn(s);
        }
        if (lane == 0) ctbuf[par][w] = ctv;
        __syncthreads();   // single barrier per round (double-buffered ctbuf)

        int first = -1; int pprev = 0, pfirst = 0, plast = 0;
#pragma unroll
        for (int i = 0; i < NW; i++) {
            int p = lo + i * stride;
            if (p < hi) {
                if (first < 0) {
                    if (__fsub_rn(ctbuf[par][i], nc) >= -TOL) { first = i; pfirst = p; }
                    else pprev = p;
                }
                plast = p;
            }
        }
        if (first >= 0) {
            ct_hi = ctbuf[par][first];
            hi = pfirst;
            if (first > 0) lo = pprev + 1;
        } else {
            lo = plast + 1;
        }
        par ^= 1;
    }

    // ---- band check + output (float4 stores) ----
    float sc = 1.0f;
    if (hi < NT) {
        float g = __fsub_rn(ct_hi, nc);               // >= -TOL by construction
        if (fabsf(g) <= TOL) {
            float tj = __fsub_rn(1.0f, __fmul_rn(TSTEP, (float)hi));
            sc = __frcp_rn(tj);
        }
    }
    if (tid < 250) {
        float4 o;
        o.x = rv.x * sc; o.y = rv.y * sc; o.z = rv.z * sc; o.w = rv.w * sc;
        ((float4*)orow)[tid] = o;
    }
}

extern "C" void kernel_launch(void* const* d_in, const int* in_sizes, int n_in,
                              void* d_out, int out_size) {
    const float* logits = (const float*)d_in[0];
    float* out = (float*)d_out;
    int B = in_sizes[0] / NCLS;   // 128 rows
    logit_compression_kernel<<<B, NTHREADS>>>(logits, out);
}